// round 7
// baseline (speedup 1.0000x reference)
#include <cuda_runtime.h>
#include <math.h>

#define H 1024
#define H4 256          // H/4 (float4 count)
#define V 50000
#define E 602
#define S 400
#define NB 148          // blocks == SMs (B200)
#define TPB 1024
#define NWARP 32        // TPB/32
#define GWARPS (NB*NWARP)   // 4736
#define NCHUNK 16
#define SPC 25          // S / NCHUNK

// phase-5 bulk-async tile pipeline
#define ROWS_PER_TILE 16
#define TILE_FLOATS   (ROWS_PER_TILE*H)          // 16384 floats
#define TILE_BYTES    (TILE_FLOATS*4)            // 65536 B
#define NBUF 3
#define DYN_SMEM (NBUF*TILE_BYTES)               // 196608 B
#define NCONS 16                                 // consumer warps
#define ROWS_PER_BLK ((V + NB - 1)/NB)           // 338

// ---------------- scratch (static device globals; no allocs) ----------------
__device__ float g_gi[3*H];
__device__ float g_gh[3*H];
__device__ float g_q[H];
__device__ float g_scores[S];
__device__ float g_attn_part[NCHUNK][H];
__device__ float g_pg_part[NCHUNK][E];
__device__ float g_ff[H];
__device__ float g_logits[V];
__device__ float g_maxpart[NB];
__device__ float g_sumpart[NB];
__device__ volatile unsigned g_flags[NB];   // zero-initialized; monotonic across replays

// ---------------- helpers ----------------
__device__ __forceinline__ float warpReduceSum(float v) {
#pragma unroll
    for (int o = 16; o > 0; o >>= 1) v += __shfl_xor_sync(0xffffffffu, v, o);
    return v;
}
__device__ __forceinline__ float warpReduceMax(float v) {
#pragma unroll
    for (int o = 16; o > 0; o >>= 1) v = fmaxf(v, __shfl_xor_sync(0xffffffffu, v, o));
    return v;
}
__device__ __forceinline__ float blockReduceSum(float v) {
    __shared__ float sh[33];
    __syncthreads();
    int lane = threadIdx.x & 31, wid = threadIdx.x >> 5;
    v = warpReduceSum(v);
    if (lane == 0) sh[wid] = v;
    __syncthreads();
    float r = (threadIdx.x < NWARP) ? sh[threadIdx.x] : 0.f;
    if (wid == 0) {
        r = warpReduceSum(r);
        if (lane == 0) sh[32] = r;
    }
    __syncthreads();
    return sh[32];
}
__device__ __forceinline__ float blockReduceMax(float v) {
    __shared__ float sh[33];
    __syncthreads();
    int lane = threadIdx.x & 31, wid = threadIdx.x >> 5;
    v = warpReduceMax(v);
    if (lane == 0) sh[wid] = v;
    __syncthreads();
    float r = (threadIdx.x < NWARP) ? sh[threadIdx.x] : -3.4e38f;
    if (wid == 0) {
        r = warpReduceMax(r);
        if (lane == 0) sh[32] = r;
    }
    __syncthreads();
    return sh[32];
}

// warp-collective partial dot (no reduce); b generic (global or shared)
__device__ __forceinline__ float warp_dot4_nr(const float* __restrict__ a,
                                              const float* __restrict__ b, int n4) {
    const float4* a4 = reinterpret_cast<const float4*>(a);
    const float4* b4 = reinterpret_cast<const float4*>(b);
    int lane = threadIdx.x & 31;
    float s = 0.f;
#pragma unroll 8
    for (int k = lane; k < n4; k += 32) {
        float4 x = a4[k];
        float4 y = b4[k];
        s = fmaf(x.x, y.x, fmaf(x.y, y.y, fmaf(x.z, y.z, fmaf(x.w, y.w, s))));
    }
    return s;
}
__device__ __forceinline__ float warp_dot4(const float* __restrict__ a,
                                           const float* __restrict__ b, int n4) {
    return warpReduceSum(warp_dot4_nr(a, b, n4));
}

__device__ __forceinline__ float sigmoidf_(float x) { return 1.f / (1.f + expf(-x)); }

// ---------------- mbarrier / bulk-async PTX helpers ----------------
__device__ __forceinline__ unsigned smem_u32(const void* p) {
    return (unsigned)__cvta_generic_to_shared(p);
}
__device__ __forceinline__ void mbar_init(unsigned mbar, unsigned count) {
    asm volatile("mbarrier.init.shared.b64 [%0], %1;" :: "r"(mbar), "r"(count) : "memory");
}
__device__ __forceinline__ void mbar_expect_tx(unsigned mbar, unsigned bytes) {
    asm volatile("mbarrier.arrive.expect_tx.shared.b64 _, [%0], %1;"
                 :: "r"(mbar), "r"(bytes) : "memory");
}
__device__ __forceinline__ void mbar_arrive(unsigned mbar) {
    asm volatile("mbarrier.arrive.shared.b64 _, [%0];" :: "r"(mbar) : "memory");
}
__device__ __forceinline__ void mbar_wait(unsigned mbar, unsigned parity) {
    asm volatile(
        "{\n\t"
        ".reg .pred P;\n\t"
        "WAITLP_%=:\n\t"
        "mbarrier.try_wait.parity.acquire.cta.shared::cta.b64 P, [%0], %1;\n\t"
        "@!P bra WAITLP_%=;\n\t"
        "}"
        :: "r"(mbar), "r"(parity) : "memory");
}
__device__ __forceinline__ void bulk_g2s(unsigned dst, const void* src,
                                         unsigned bytes, unsigned mbar) {
    asm volatile(
        "cp.async.bulk.shared::cluster.global.mbarrier::complete_tx::bytes "
        "[%0], [%1], %2, [%3];"
        :: "r"(dst), "l"(src), "r"(bytes), "r"(mbar) : "memory");
}

// flat grid barrier (monotonic per-block flags; replay-safe)
__device__ __forceinline__ void grid_bar(unsigned myflag) {
    __syncthreads();
    if (threadIdx.x == 0) {
        __threadfence();
        g_flags[blockIdx.x] = myflag;
    }
    if (threadIdx.x < NB) {
        while (g_flags[threadIdx.x] < myflag) { }
    }
    __syncthreads();
}

// ---------------- the single persistent kernel ----------------
__global__ void __launch_bounds__(TPB, 1)
decoder_step(const int* __restrict__ idx,
             const float* __restrict__ hidden,
             const float* __restrict__ enc,
             const float* __restrict__ trigger,
             const float* __restrict__ pg_mat,
             const float* __restrict__ emb,
             const float* __restrict__ attn_W,
             const float* __restrict__ comb_W,
             const float* __restrict__ comb_b,
             const float* __restrict__ W_ih,
             const float* __restrict__ W_hh,
             const float* __restrict__ b_ih,
             const float* __restrict__ b_hh,
             const float* __restrict__ out_W,
             const float* __restrict__ out_b,
             const float* __restrict__ wh_W,
             const float* __restrict__ ws_W,
             const float* __restrict__ wx_W,
             const float* __restrict__ wx_b,
             float* __restrict__ out, int out_size) {
    extern __shared__ __align__(128) float dynbuf[];   // NBUF tiles

    __shared__ __align__(16) float sh_h[H];   // h_new
    __shared__ __align__(16) float sh_a[H];   // attn_applied
    __shared__ __align__(16) float sh_f[H];   // ff
    __shared__ float sh_aw[S];                // softmax weights (chunk blocks)
    __shared__ float sh_m[NWARP], sh_s[NWARP];
    __shared__ __align__(8) unsigned long long s_full[NBUF], s_empty[NBUF];

    const int tid  = threadIdx.x;
    const int bid  = blockIdx.x;
    const int lane = tid & 31;
    const int wid  = tid >> 5;

    unsigned barflag = g_flags[bid];          // own flag: race-free entry read

    // mbarrier init for the phase-5 pipeline
    if (tid == 0) {
#pragma unroll
        for (int i = 0; i < NBUF; i++) {
            mbar_init(smem_u32(&s_full[i]), 1);
            mbar_init(smem_u32(&s_empty[i]), NCONS);
        }
    }
    __syncthreads();

    const int token = idx[0];
    const float* erow = emb + (size_t)token * H;

    // ---- Phase 0: GRU gate pre-activations (3072 warp-dots) ----
    for (int t = wid * NB + bid; t < 3 * H; t += GWARPS) {
        const float* wrow = W_ih + (size_t)t * 2 * H;
        float gi = warpReduceSum(warp_dot4_nr(wrow, erow, H4)
                               + warp_dot4_nr(wrow + H, trigger, H4));
        float gh = warp_dot4(W_hh + (size_t)t * H, hidden, H4);
        if (lane == 0) {
            g_gi[t] = gi + __ldg(b_ih + t);
            g_gh[t] = gh + __ldg(b_hh + t);
        }
    }
    grid_bar(++barflag);

    // ---- Phase 1: h_new (redundant per block, into smem) + q = attn_W @ h ----
    for (int j = tid; j < H; j += TPB) {
        float gr = g_gi[j] + g_gh[j];
        float gz = g_gi[H + j] + g_gh[H + j];
        float r = sigmoidf_(gr);
        float z = sigmoidf_(gz);
        float n = tanhf(g_gi[2 * H + j] + r * g_gh[2 * H + j]);
        float hn = (1.f - z) * n + z * __ldg(hidden + j);
        sh_h[j] = hn;
        if (bid == 0 && (V + E + j) < out_size) out[V + E + j] = hn;
    }
    __syncthreads();
    for (int r = wid * NB + bid; r < H; r += GWARPS) {
        float v = warp_dot4(attn_W + (size_t)r * H, sh_h, H4);
        if (lane == 0) g_q[r] = v;
    }
    grid_bar(++barflag);

    // ---- Phase 2: scores = enc @ q ----
    for (int r = wid * NB + bid; r < S; r += GWARPS) {
        float v = warp_dot4(enc + (size_t)r * H, g_q, H4);
        if (lane == 0) g_scores[r] = v;
    }
    grid_bar(++barflag);

    // ---- Phase 3: (chunk blocks) redundant softmax + attn/pg chunk partials ----
    if (bid < NCHUNK) {
        float v = (tid < S) ? g_scores[tid] : -3.4e38f;
        float m = blockReduceMax(v);
        float e = (tid < S) ? expf(v - m) : 0.f;
        float sum = blockReduceSum(e);
        if (tid < S) sh_aw[tid] = e / sum;
        __syncthreads();
        if (bid == 0 && tid < S && (V + E + H + tid) < out_size)
            out[V + E + H + tid] = sh_aw[tid];
        const int c = bid;
        for (int j = tid; j < H; j += TPB) {
            float acc = 0.f, accp = 0.f;
#pragma unroll
            for (int k = 0; k < SPC; k++) {
                int s = c * SPC + k;
                float w = sh_aw[s];
                acc = fmaf(w, __ldg(enc + (size_t)s * H + j), acc);
                if (j < E) accp = fmaf(w, __ldg(pg_mat + (size_t)s * E + j), accp);
            }
            g_attn_part[c][j] = acc;
            if (j < E) g_pg_part[c][j] = accp;
        }
    }
    grid_bar(++barflag);

    // ---- Phase 4: attn_applied + p_gen (redundant per block) + pg tail + ff ----
    float pgen;
    {
        float val = 0.f;
        for (int j = tid; j < H; j += TPB) {
            float a = 0.f;
#pragma unroll
            for (int c = 0; c < NCHUNK; c++) a += g_attn_part[c][j];
            sh_a[j] = a;
            val += __ldg(wh_W + j) * a + __ldg(ws_W + j) * sh_h[j]
                 + __ldg(wx_W + j) * erow[j];
        }
        float t = blockReduceSum(val);   // also fences sh_a writes for the block
        pgen = sigmoidf_(t + __ldg(wx_b));
    }
    if (bid == 0) {
        for (int j = tid; j < E; j += TPB) {
            float p = 0.f;
#pragma unroll
            for (int c = 0; c < NCHUNK; c++) p += g_pg_part[c][j];
            if ((V + j) < out_size) out[V + j] = logf(p * (1.f - pgen));
        }
    }
    for (int r = wid * NB + bid; r < H; r += GWARPS) {
        const float* row = comb_W + (size_t)r * 2 * H;
        float v = warpReduceSum(warp_dot4_nr(row, sh_h, H4)
                              + warp_dot4_nr(row + H, sh_a, H4));
        if (lane == 0) g_ff[r] = fmaxf(v + __ldg(comb_b + r), 0.f);
    }
    grid_bar(++barflag);

    // ---- Phase 5: logits via bulk-async tile pipeline + online (max,sum) ----
    for (int j = tid; j < H; j += TPB) sh_f[j] = g_ff[j];
    __syncthreads();

    const int r0 = bid * ROWS_PER_BLK;
    const int r1 = (r0 + ROWS_PER_BLK < V) ? (r0 + ROWS_PER_BLK) : V;
    const int nrows = r1 - r0;
    const int ntiles = (nrows + ROWS_PER_TILE - 1) / ROWS_PER_TILE;

    float m_run = -INFINITY, s_run = 0.f;

    if (tid == TPB - 1) {
        // producer: stream tiles of out_W into the smem ring
        for (int t = 0; t < ntiles; t++) {
            int buf = t % NBUF;
            unsigned u = (unsigned)(t / NBUF);
            mbar_wait(smem_u32(&s_empty[buf]), (u ^ 1u) & 1u);  // first pass free
            int tr0 = r0 + t * ROWS_PER_TILE;
            int trows = (r1 - tr0 < ROWS_PER_TILE) ? (r1 - tr0) : ROWS_PER_TILE;
            unsigned bytes = (unsigned)trows * (H * 4);
            unsigned fullb = smem_u32(&s_full[buf]);
            mbar_expect_tx(fullb, bytes);
            bulk_g2s(smem_u32(dynbuf + (size_t)buf * TILE_FLOATS),
                     out_W + (size_t)tr0 * H, bytes, fullb);
        }
    } else if (wid < NCONS) {
        // consumers: one row per warp per tile, dot from smem
        const float4* f4 = reinterpret_cast<const float4*>(sh_f);
        for (int t = 0; t < ntiles; t++) {
            int buf = t % NBUF;
            unsigned u = (unsigned)(t / NBUF);
            mbar_wait(smem_u32(&s_full[buf]), u & 1u);
            int row = r0 + t * ROWS_PER_TILE + wid;
            if (row < r1) {
                const float4* r4 = reinterpret_cast<const float4*>(
                    dynbuf + (size_t)buf * TILE_FLOATS + (size_t)wid * H);
                float sA = 0.f, sB = 0.f;
#pragma unroll
                for (int k = 0; k < 4; k++) {
                    int i0 = lane + k * 64, i1 = i0 + 32;
                    float4 x0 = r4[i0], y0 = f4[i0];
                    float4 x1 = r4[i1], y1 = f4[i1];
                    sA = fmaf(x0.x, y0.x, fmaf(x0.y, y0.y, fmaf(x0.z, y0.z, fmaf(x0.w, y0.w, sA))));
                    sB = fmaf(x1.x, y1.x, fmaf(x1.y, y1.y, fmaf(x1.z, y1.z, fmaf(x1.w, y1.w, sB))));
                }
                float l = warpReduceSum(sA + sB) + __ldg(out_b + row);
                if (lane == 0) g_logits[row] = l;
                float mn = fmaxf(m_run, l);
                s_run = s_run * expf(m_run - mn) + expf(l - mn);
                m_run = mn;
            }
            // warp is past all smem reads of this tile (post-reduce) -> release
            if (lane == 0) mbar_arrive(smem_u32(&s_empty[buf]));
        }
    }

    if (lane == 0) { sh_m[wid] = m_run; sh_s[wid] = s_run; }
    __syncthreads();
    if (tid == 0) {
        float mb = -INFINITY;
#pragma unroll
        for (int k = 0; k < NWARP; k++) mb = fmaxf(mb, sh_m[k]);
        float sb = 0.f;
#pragma unroll
        for (int k = 0; k < NWARP; k++) sb += sh_s[k] * expf(sh_m[k] - mb);
        g_maxpart[bid] = mb;
        g_sumpart[bid] = sb;
    }
    grid_bar(++barflag);

    // ---- Phase 6: combine 148 (m,s) pairs (redundant) + write vocab logprobs ----
    {
        float m = (tid < NB) ? g_maxpart[tid] : -INFINITY;
        float gm = blockReduceMax(m);
        float contrib = (tid < NB) ? g_sumpart[tid] * expf(g_maxpart[tid] - gm) : 0.f;
        float tot = blockReduceSum(contrib);
        float logc = gm + logf(tot) - logf(pgen);
        int j = bid * TPB + tid;
        if (j < V) out[j] = g_logits[j] - logc;
    }
}

// ---------------- launch ----------------
extern "C" void kernel_launch(void* const* d_in, const int* in_sizes, int n_in,
                              void* d_out, int out_size) {
    const int*   idx     = (const int*)  d_in[0];
    const float* hidden  = (const float*)d_in[1];
    const float* enc     = (const float*)d_in[2];
    const float* trigger = (const float*)d_in[3];
    const float* pg_mat  = (const float*)d_in[4];
    const float* emb     = (const float*)d_in[5];
    const float* attn_W  = (const float*)d_in[6];
    const float* comb_W  = (const float*)d_in[7];
    const float* comb_b  = (const float*)d_in[8];
    const float* W_ih    = (const float*)d_in[9];
    const float* W_hh    = (const float*)d_in[10];
    const float* b_ih    = (const float*)d_in[11];
    const float* b_hh    = (const float*)d_in[12];
    const float* out_W   = (const float*)d_in[13];
    const float* out_b   = (const float*)d_in[14];
    const float* wh_W    = (const float*)d_in[15];
    const float* ws_W    = (const float*)d_in[16];
    const float* wx_W    = (const float*)d_in[17];
    const float* wx_b    = (const float*)d_in[18];
    float* out = (float*)d_out;

    (void)in_sizes; (void)n_in;

    static int smem_set = 0;
    if (!smem_set) {
        cudaFuncSetAttribute(decoder_step,
                             cudaFuncAttributeMaxDynamicSharedMemorySize, DYN_SMEM);
        smem_set = 1;
    }

    decoder_step<<<NB, TPB, DYN_SMEM>>>(idx, hidden, enc, trigger, pg_mat, emb,
                                        attn_W, comb_W, comb_b, W_ih, W_hh,
                                        b_ih, b_hh, out_W, out_b, wh_W, ws_W,
                                        wx_W, wx_b, out, out_size);
}

// round 9
// speedup vs baseline: 1.1031x; 1.1031x over previous
#include <cuda_runtime.h>
#include <math.h>

#define H 1024
#define H4 256          // H/4 (float4 count)
#define V 50000
#define E 602
#define S 400
#define NB 148          // blocks == SMs (B200)
#define TPB 512
#define NWARP 16        // TPB/32
#define GWARPS (NB*NWARP)   // 2368
#define NCHUNK 16
#define SPC 25          // S / NCHUNK

// ---------------- scratch (static device globals; no allocs) ----------------
__device__ float g_gi[3*H];
__device__ float g_gh[3*H];
__device__ float g_q[H];
__device__ float g_scores[S];
__device__ float g_attn_part[NCHUNK][H];
__device__ float g_pg_part[NCHUNK][E];
__device__ float g_ff[H];
__device__ float g_logits[V];
__device__ float g_maxpart[NB];
__device__ float g_sumpart[NB];
__device__ volatile unsigned g_flags[NB];   // zero-initialized; monotonic across replays

// ---------------- helpers ----------------
__device__ __forceinline__ float fma4(float4 a, float4 b, float s) {
    return fmaf(a.x, b.x, fmaf(a.y, b.y, fmaf(a.z, b.z, fmaf(a.w, b.w, s))));
}
__device__ __forceinline__ float warpReduceSum(float v) {
#pragma unroll
    for (int o = 16; o > 0; o >>= 1) v += __shfl_xor_sync(0xffffffffu, v, o);
    return v;
}
__device__ __forceinline__ float warpReduceMax(float v) {
#pragma unroll
    for (int o = 16; o > 0; o >>= 1) v = fmaxf(v, __shfl_xor_sync(0xffffffffu, v, o));
    return v;
}
__device__ __forceinline__ float blockReduceSum(float v) {
    __shared__ float sh[33];
    __syncthreads();
    int lane = threadIdx.x & 31, wid = threadIdx.x >> 5;
    v = warpReduceSum(v);
    if (lane == 0) sh[wid] = v;
    __syncthreads();
    float r = (threadIdx.x < NWARP) ? sh[threadIdx.x] : 0.f;
    if (wid == 0) {
        r = warpReduceSum(r);
        if (lane == 0) sh[32] = r;
    }
    __syncthreads();
    return sh[32];
}
__device__ __forceinline__ float blockReduceMax(float v) {
    __shared__ float sh[33];
    __syncthreads();
    int lane = threadIdx.x & 31, wid = threadIdx.x >> 5;
    v = warpReduceMax(v);
    if (lane == 0) sh[wid] = v;
    __syncthreads();
    float r = (threadIdx.x < NWARP) ? sh[threadIdx.x] : -3.4e38f;
    if (wid == 0) {
        r = warpReduceMax(r);
        if (lane == 0) sh[32] = r;
    }
    __syncthreads();
    return sh[32];
}

// warp-collective partial dot (no reduce)
__device__ __forceinline__ float warp_dot4_nr(const float* __restrict__ a,
                                              const float* __restrict__ b, int n4) {
    const float4* a4 = reinterpret_cast<const float4*>(a);
    const float4* b4 = reinterpret_cast<const float4*>(b);
    int lane = threadIdx.x & 31;
    float s = 0.f;
#pragma unroll 8
    for (int k = lane; k < n4; k += 32) s = fma4(a4[k], b4[k], s);
    return s;
}
__device__ __forceinline__ float warp_dot4(const float* __restrict__ a,
                                           const float* __restrict__ b, int n4) {
    return warpReduceSum(warp_dot4_nr(a, b, n4));
}

__device__ __forceinline__ float sigmoidf_(float x) { return 1.f / (1.f + expf(-x)); }

// flat grid barrier (monotonic per-block flags; replay-safe)
__device__ __forceinline__ void grid_bar(unsigned myflag) {
    __syncthreads();
    if (threadIdx.x == 0) {
        __threadfence();
        g_flags[blockIdx.x] = myflag;
    }
    if (threadIdx.x < NB) {
        while (g_flags[threadIdx.x] < myflag) { }
    }
    __syncthreads();
}

// ---------------- the single persistent kernel ----------------
__global__ void __launch_bounds__(TPB, 1)
decoder_step(const int* __restrict__ idx,
             const float* __restrict__ hidden,
             const float* __restrict__ enc,
             const float* __restrict__ trigger,
             const float* __restrict__ pg_mat,
             const float* __restrict__ emb,
             const float* __restrict__ attn_W,
             const float* __restrict__ comb_W,
             const float* __restrict__ comb_b,
             const float* __restrict__ W_ih,
             const float* __restrict__ W_hh,
             const float* __restrict__ b_ih,
             const float* __restrict__ b_hh,
             const float* __restrict__ out_W,
             const float* __restrict__ out_b,
             const float* __restrict__ wh_W,
             const float* __restrict__ ws_W,
             const float* __restrict__ wx_W,
             const float* __restrict__ wx_b,
             float* __restrict__ out, int out_size) {
    __shared__ __align__(16) float sh_h[H];   // h_new
    __shared__ __align__(16) float sh_a[H];   // attn_applied
    __shared__ __align__(16) float sh_f[H];   // ff
    __shared__ float sh_aw[S];                // softmax weights (chunk blocks)
    __shared__ float sh_m[NWARP], sh_s[NWARP];

    const int tid  = threadIdx.x;
    const int bid  = blockIdx.x;
    const int lane = tid & 31;
    const int wid  = tid >> 5;
    const int gw   = bid * NWARP + wid;

    unsigned barflag = g_flags[bid];          // own flag: race-free entry read

    const int token = idx[0];
    const float* erow = emb + (size_t)token * H;

    // ---- Phase 0: GRU gate pre-activations; 3 load streams, fused reduce ----
    {
        const float4* e4 = reinterpret_cast<const float4*>(erow);
        const float4* t4 = reinterpret_cast<const float4*>(trigger);
        const float4* h4 = reinterpret_cast<const float4*>(hidden);
        for (int t = wid * NB + bid; t < 3 * H; t += GWARPS) {
            const float4* wi = reinterpret_cast<const float4*>(W_ih + (size_t)t * 2 * H);
            const float4* wh = reinterpret_cast<const float4*>(W_hh + (size_t)t * H);
            float sgi = 0.f, sgh = 0.f;
#pragma unroll 8
            for (int k = lane; k < H4; k += 32) {
                sgi = fma4(wi[k], e4[k], sgi);
                sgi = fma4(wi[k + H4], t4[k], sgi);
                sgh = fma4(wh[k], h4[k], sgh);
            }
#pragma unroll
            for (int o = 16; o > 0; o >>= 1) {
                sgi += __shfl_xor_sync(0xffffffffu, sgi, o);
                sgh += __shfl_xor_sync(0xffffffffu, sgh, o);
            }
            if (lane == 0) {
                g_gi[t] = sgi + __ldg(b_ih + t);
                g_gh[t] = sgh + __ldg(b_hh + t);
            }
        }
    }
    grid_bar(++barflag);

    // ---- Phase 1: h_new (redundant per block, into smem) + q = attn_W @ h ----
    for (int j = tid; j < H; j += TPB) {
        float gr = g_gi[j] + g_gh[j];
        float gz = g_gi[H + j] + g_gh[H + j];
        float r = sigmoidf_(gr);
        float z = sigmoidf_(gz);
        float n = tanhf(g_gi[2 * H + j] + r * g_gh[2 * H + j]);
        float hn = (1.f - z) * n + z * __ldg(hidden + j);
        sh_h[j] = hn;
        if (bid == 0 && (V + E + j) < out_size) out[V + E + j] = hn;
    }
    __syncthreads();
    for (int r = wid * NB + bid; r < H; r += GWARPS) {
        float v = warp_dot4(attn_W + (size_t)r * H, sh_h, H4);
        if (lane == 0) g_q[r] = v;
    }
    grid_bar(++barflag);

    // ---- Phase 2: scores = enc @ q ----
    for (int r = wid * NB + bid; r < S; r += GWARPS) {
        float v = warp_dot4(enc + (size_t)r * H, g_q, H4);
        if (lane == 0) g_scores[r] = v;
    }
    grid_bar(++barflag);

    // ---- Phase 3: (chunk blocks) redundant softmax + attn/pg chunk partials ----
    if (bid < NCHUNK) {
        float v = (tid < S) ? g_scores[tid] : -3.4e38f;
        float m = blockReduceMax(v);
        float e = (tid < S) ? expf(v - m) : 0.f;
        float sum = blockReduceSum(e);
        if (tid < S) sh_aw[tid] = e / sum;
        __syncthreads();
        if (bid == 0 && tid < S && (V + E + H + tid) < out_size)
            out[V + E + H + tid] = sh_aw[tid];
        const int c = bid;
        for (int j = tid; j < H; j += TPB) {
            float acc = 0.f, accp = 0.f;
#pragma unroll
            for (int k = 0; k < SPC; k++) {
                int s = c * SPC + k;
                float w = sh_aw[s];
                acc = fmaf(w, __ldg(enc + (size_t)s * H + j), acc);
                if (j < E) accp = fmaf(w, __ldg(pg_mat + (size_t)s * E + j), accp);
            }
            g_attn_part[c][j] = acc;
            if (j < E) g_pg_part[c][j] = accp;
        }
    }
    grid_bar(++barflag);

    // ---- Phase 4: attn_applied + p_gen (redundant per block) + pg tail + ff ----
    float pgen;
    {
        float val = 0.f;
        for (int j = tid; j < H; j += TPB) {
            float a = 0.f;
#pragma unroll
            for (int c = 0; c < NCHUNK; c++) a += g_attn_part[c][j];
            sh_a[j] = a;
            val += __ldg(wh_W + j) * a + __ldg(ws_W + j) * sh_h[j]
                 + __ldg(wx_W + j) * erow[j];
        }
        float t = blockReduceSum(val);   // also fences sh_a writes for the block
        pgen = sigmoidf_(t + __ldg(wx_b));
    }
    if (bid == 0) {
        for (int j = tid; j < E; j += TPB) {
            float p = 0.f;
#pragma unroll
            for (int c = 0; c < NCHUNK; c++) p += g_pg_part[c][j];
            if ((V + j) < out_size) out[V + j] = logf(p * (1.f - pgen));
        }
    }
    for (int r = wid * NB + bid; r < H; r += GWARPS) {
        const float* row = comb_W + (size_t)r * 2 * H;
        float v = warpReduceSum(warp_dot4_nr(row, sh_h, H4)
                              + warp_dot4_nr(row + H, sh_a, H4));
        if (lane == 0) g_ff[r] = fmaxf(v + __ldg(comb_b + r), 0.f);
    }
    grid_bar(++barflag);

    // ---- Phase 5: logits, 4 rows per warp (ILP) + online (max,sum) ----
    for (int j = tid; j < H; j += TPB) sh_f[j] = g_ff[j];
    __syncthreads();
    {
        const float4* f4 = reinterpret_cast<const float4*>(sh_f);
        float m_run = -INFINITY, s_run = 0.f;
        for (int j = gw; j < V; j += 4 * GWARPS) {
            int j0 = j;
            int j1 = j + GWARPS;     bool v1 = j1 < V; if (!v1) j1 = V - 1;
            int j2 = j + 2 * GWARPS; bool v2 = j2 < V; if (!v2) j2 = V - 1;
            int j3 = j + 3 * GWARPS; bool v3 = j3 < V; if (!v3) j3 = V - 1;
            const float4* r0 = reinterpret_cast<const float4*>(out_W + (size_t)j0 * H);
            const float4* r1 = reinterpret_cast<const float4*>(out_W + (size_t)j1 * H);
            const float4* r2 = reinterpret_cast<const float4*>(out_W + (size_t)j2 * H);
            const float4* r3 = reinterpret_cast<const float4*>(out_W + (size_t)j3 * H);
            float a0 = 0.f, a1 = 0.f, a2 = 0.f, a3 = 0.f;
#pragma unroll 8
            for (int k = lane; k < H4; k += 32) {
                float4 f = f4[k];
                a0 = fma4(r0[k], f, a0);
                a1 = fma4(r1[k], f, a1);
                a2 = fma4(r2[k], f, a2);
                a3 = fma4(r3[k], f, a3);
            }
#pragma unroll
            for (int o = 16; o > 0; o >>= 1) {
                a0 += __shfl_xor_sync(0xffffffffu, a0, o);
                a1 += __shfl_xor_sync(0xffffffffu, a1, o);
                a2 += __shfl_xor_sync(0xffffffffu, a2, o);
                a3 += __shfl_xor_sync(0xffffffffu, a3, o);
            }
            float l0 = a0 + __ldg(out_b + j0);
            float l1 = a1 + __ldg(out_b + j1);
            float l2 = a2 + __ldg(out_b + j2);
            float l3 = a3 + __ldg(out_b + j3);
            if (lane == 0) {
                g_logits[j0] = l0;
                if (v1) g_logits[j1] = l1;
                if (v2) g_logits[j2] = l2;
                if (v3) g_logits[j3] = l3;
            }
            // online (max,sum) over the valid subset
            float mx = l0;
            if (v1) mx = fmaxf(mx, l1);
            if (v2) mx = fmaxf(mx, l2);
            if (v3) mx = fmaxf(mx, l3);
            float mn = fmaxf(m_run, mx);
            float s = expf(l0 - mn);
            if (v1) s += expf(l1 - mn);
            if (v2) s += expf(l2 - mn);
            if (v3) s += expf(l3 - mn);
            s_run = s_run * expf(m_run - mn) + s;
            m_run = mn;
        }
        if (lane == 0) { sh_m[wid] = m_run; sh_s[wid] = s_run; }
        __syncthreads();
        if (tid == 0) {
            float mb = -INFINITY;
#pragma unroll
            for (int k = 0; k < NWARP; k++) mb = fmaxf(mb, sh_m[k]);
            float sb = 0.f;
#pragma unroll
            for (int k = 0; k < NWARP; k++) sb += sh_s[k] * expf(sh_m[k] - mb);
            g_maxpart[bid] = mb;
            g_sumpart[bid] = sb;
        }
    }
    grid_bar(++barflag);

    // ---- Phase 6: combine 148 (m,s) pairs (redundant) + write vocab logprobs ----
    {
        float m = (tid < NB) ? g_maxpart[tid] : -INFINITY;
        float gm = blockReduceMax(m);
        float contrib = (tid < NB) ? g_sumpart[tid] * expf(g_maxpart[tid] - gm) : 0.f;
        float tot = blockReduceSum(contrib);
        float logc = gm + logf(tot) - logf(pgen);
        int j = bid * TPB + tid;
        if (j < V) out[j] = g_logits[j] - logc;
    }
}

// ---------------- launch ----------------
extern "C" void kernel_launch(void* const* d_in, const int* in_sizes, int n_in,
                              void* d_out, int out_size) {
    const int*   idx     = (const int*)  d_in[0];
    const float* hidden  = (const float*)d_in[1];
    const float* enc     = (const float*)d_in[2];
    const float* trigger = (const float*)d_in[3];
    const float* pg_mat  = (const float*)d_in[4];
    const float* emb     = (const float*)d_in[5];
    const float* attn_W  = (const float*)d_in[6];
    const float* comb_W  = (const float*)d_in[7];
    const float* comb_b  = (const float*)d_in[8];
    const float* W_ih    = (const float*)d_in[9];
    const float* W_hh    = (const float*)d_in[10];
    const float* b_ih    = (const float*)d_in[11];
    const float* b_hh    = (const float*)d_in[12];
    const float* out_W   = (const float*)d_in[13];
    const float* out_b   = (const float*)d_in[14];
    const float* wh_W    = (const float*)d_in[15];
    const float* ws_W    = (const float*)d_in[16];
    const float* wx_W    = (const float*)d_in[17];
    const float* wx_b    = (const float*)d_in[18];
    float* out = (float*)d_out;

    (void)in_sizes; (void)n_in;

    decoder_step<<<NB, TPB>>>(idx, hidden, enc, trigger, pg_mat, emb, attn_W,
                              comb_W, comb_b, W_ih, W_hh, b_ih, b_hh,
                              out_W, out_b, wh_W, ws_W, wx_W, wx_b,
                              out, out_size);
}